// round 15
// baseline (speedup 1.0000x reference)
#include <cuda_runtime.h>
#include <cuda_bf16.h>
#include <math.h>
#include <stdint.h>

#define NB     4096
#define NPER   2000
#define WPB    4                   // warps (events) per block
#define THREADS (WPB * 32)         // 128
#define NBLK   (NB / WPB)          // 1024 blocks: near-perfect wave balance
#define CROWS  125                 // rows per chunk (2000 B)
#define NCH    16                  // 16 * 125 = 2000 rows
#define NSTAGE 3                   // per-warp smem ring depth

// Scratch (no device allocation allowed anywhere).
__device__ double g_part[NBLK];
__device__ unsigned int g_cnt = 0;

#define ACCUM(v)                                   \
    do {                                           \
        acc[0] += (v).x; acc[1] += (v).y;          \
        acc[2] += (v).z; acc[3] += (v).w;          \
        acc[4]  = fmaf((v).x, (v).x, acc[4]);      \
        acc[5]  = fmaf((v).x, (v).y, acc[5]);      \
        acc[6]  = fmaf((v).x, (v).z, acc[6]);      \
        acc[7]  = fmaf((v).x, (v).w, acc[7]);      \
        acc[8]  = fmaf((v).y, (v).y, acc[8]);      \
        acc[9]  = fmaf((v).y, (v).z, acc[9]);      \
        acc[10] = fmaf((v).y, (v).w, acc[10]);     \
        acc[11] = fmaf((v).z, (v).z, acc[11]);     \
        acc[12] = fmaf((v).z, (v).w, acc[12]);     \
        acc[13] = fmaf((v).w, (v).w, acc[13]);     \
    } while (0)

__device__ __forceinline__ void cp16(uint32_t dst, const void* src) {
    asm volatile("cp.async.cg.shared.global [%0], [%1], 16;"
                 :: "r"(dst), "l"(src) : "memory");
}
template <int N>
__device__ __forceinline__ void wait_group() {
    asm volatile("cp.async.wait_group %0;" :: "n"(N) : "memory");
}

__global__ void __launch_bounds__(THREADS) llfill_fused_kernel(
        const float4* __restrict__ x, float* __restrict__ out) {
    // Per-warp 3-stage ring: 4 warps x 3 stages x 125 float4 = 24000 B.
    __shared__ alignas(16) float4 sbuf[WPB][NSTAGE][CROWS];
    __shared__ float spen[WPB];
    __shared__ bool is_last;

    const int lane = threadIdx.x & 31;
    const int warp = threadIdx.x >> 5;
    const int b = blockIdx.x * WPB + warp;          // one warp per event
    const char* evb = (const char*)(x + (size_t)b * NPER);
    const uint32_t sb = (uint32_t)__cvta_generic_to_shared(&sbuf[warp][0][0]);
    const bool l4 = (lane < 29);                    // 125 = 3*32 + 29

    // Issue one chunk: each thread copies ITS OWN rows (lane+32i) G->S.
    // Per-thread groups: consume reads exactly what this thread wrote, so the
    // rolling pipeline needs no barriers and no cross-lane sync.
#define ISSUE_CHUNK(c)                                                        \
    do {                                                                      \
        const int _s = (c) % NSTAGE;                                          \
        const char* _g = evb + (size_t)(c) * (CROWS * 16) + lane * 16;        \
        const uint32_t _d = sb + _s * (CROWS * 16) + lane * 16;               \
        cp16(_d,          _g);                                                \
        cp16(_d + 512,    _g + 512);                                          \
        cp16(_d + 1024,   _g + 1024);                                        \
        if (l4) cp16(_d + 1536, _g + 1536);                                   \
        asm volatile("cp.async.commit_group;" ::: "memory");                  \
    } while (0)

    // Consume chunk c from its stage into acc (rows lane, +32, +64, [+96]).
#define CONSUME_CHUNK(c)                                                      \
    do {                                                                      \
        const float4* sp = &sbuf[warp][(c) % NSTAGE][0];                      \
        float4 v0 = sp[lane];                                                 \
        float4 v1 = sp[lane + 32];                                            \
        float4 v2 = sp[lane + 64];                                            \
        float4 v3;                                                            \
        if (l4) v3 = sp[lane + 96];                                           \
        if ((c) + 3 < NCH) ISSUE_CHUNK((c) + 3);                              \
        ACCUM(v0); ACCUM(v1); ACCUM(v2);                                      \
        if (l4) ACCUM(v3);                                                    \
    } while (0)

    ISSUE_CHUNK(0);
    ISSUE_CHUNK(1);
    ISSUE_CHUNK(2);

    // 14 accumulators: sums x,y,z,w; moments xx,xy,xz,xw,yy,yz,yw,zz,zw,ww
    float acc[14];
#pragma unroll
    for (int j = 0; j < 14; j++) acc[j] = 0.0f;

    // Main loop: while >=3 groups pending, wait_group 2 == "oldest complete".
#pragma unroll
    for (int c = 0; c < NCH - 2; c++) {
        wait_group<2>();
        CONSUME_CHUNK(c);
    }
    // Drain: pending counts are 2 then 1, so the wait depth must shrink to
    // keep guaranteeing the consumed chunk's group has completed.
    wait_group<1>();
    CONSUME_CHUNK(NCH - 2);
    wait_group<0>();
    CONSUME_CHUNK(NCH - 1);

#undef CONSUME_CHUNK
#undef ISSUE_CHUNK

    // Warp shuffle reduce of the 14 moments.
#pragma unroll
    for (int j = 0; j < 14; j++) {
        float s = acc[j];
#pragma unroll
        for (int off = 16; off; off >>= 1) s += __shfl_down_sync(0xffffffffu, s, off);
        acc[j] = s;
    }

    if (lane == 0) {
        const float invN = 1.0f / (float)NPER;
        const float m0 = acc[0] * invN, m1 = acc[1] * invN;
        const float m2 = acc[2] * invN, m3 = acc[3] * invN;

        // Covariance (symmetric), shifted by mu = trace/4 so tr(A)=0.
        float a00 = acc[4]  * invN - m0 * m0;
        float a01 = acc[5]  * invN - m0 * m1;
        float a02 = acc[6]  * invN - m0 * m2;
        float a03 = acc[7]  * invN - m0 * m3;
        float a11 = acc[8]  * invN - m1 * m1;
        float a12 = acc[9]  * invN - m1 * m2;
        float a13 = acc[10] * invN - m1 * m3;
        float a22 = acc[11] * invN - m2 * m2;
        float a23 = acc[12] * invN - m2 * m3;
        float a33 = acc[13] * invN - m3 * m3;

        const float mu = 0.25f * (a00 + a11 + a22 + a33);
        a00 -= mu; a11 -= mu; a22 -= mu; a33 -= mu;

        // p2 = tr(A^2).
        float offsq = a01*a01 + a02*a02 + a03*a03 + a12*a12 + a13*a13 + a23*a23;
        float p2 = a00*a00 + a11*a11 + a22*a22 + a33*a33 + 2.0f * offsq;

        // B = A^2 (symmetric, 10 entries).
        float b00 = a00*a00 + a01*a01 + a02*a02 + a03*a03;
        float b11 = a01*a01 + a11*a11 + a12*a12 + a13*a13;
        float b22 = a02*a02 + a12*a12 + a22*a22 + a23*a23;
        float b33 = a03*a03 + a13*a13 + a23*a23 + a33*a33;
        float b01 = a00*a01 + a01*a11 + a02*a12 + a03*a13;
        float b02 = a00*a02 + a01*a12 + a02*a22 + a03*a23;
        float b03 = a00*a03 + a01*a13 + a02*a23 + a03*a33;
        float b12 = a01*a02 + a11*a12 + a12*a22 + a13*a23;
        float b13 = a01*a03 + a11*a13 + a12*a23 + a13*a33;
        float b23 = a02*a03 + a12*a13 + a22*a23 + a23*a33;

        // p3 = tr(A^3); p4 = tr(A^4).
        float p3 = b00*a00 + b11*a11 + b22*a22 + b33*a33
                 + 2.0f * (b01*a01 + b02*a02 + b03*a03 + b12*a12 + b13*a13 + b23*a23);
        float p4 = b00*b00 + b11*b11 + b22*b22 + b33*b33
                 + 2.0f * (b01*b01 + b02*b02 + b03*b03 + b12*b12 + b13*b13 + b23*b23);

        // Char poly of trace-free A: l^4 + e2 l^2 - e3 l + e4 (Newton identities, e1=0).
        float e2 = -0.5f * p2;
        float e3 = p3 * (1.0f / 3.0f);
        float e4 = 0.25f * fmaf(0.5f * p2, p2, -p4);

        // Newton from below the smallest root (all roots real; tr=0 => lmin <= 0).
        float l = -sqrtf(p2) * 1.000001f - 1e-12f;
#pragma unroll
        for (int it = 0; it < 16; it++) {
            float t  = l * l;
            float pv = fmaf(t + e2, t, fmaf(-e3, l, e4));
            float dv = fmaf(fmaf(4.0f, t, 2.0f * e2), l, -e3);
            l -= __fdividef(pv, dv);
        }

        float eigmin = mu + l;                          // min eigenvalue of cov
        float r = mu / (eigmin + 1e-6f) - 1.0f;         // mean(eig) == trace/4 == mu
        spen[warp] = logf(fmaf(r, r, 1.0f));
    }
    __syncthreads();

    // Per-block partial (fixed order -> deterministic), last-block final reduce.
    if (threadIdx.x == 0) {
        double s = 0.0;
#pragma unroll
        for (int w = 0; w < WPB; w++) s += (double)spen[w];
        g_part[blockIdx.x] = s;
        __threadfence();
        unsigned int t = atomicInc(&g_cnt, NBLK - 1);   // wraps to 0 each launch
        is_last = (t == NBLK - 1);
    }
    __syncthreads();

    if (is_last) {
        // 128 threads reduce 1024 doubles with a fixed tree (deterministic).
        volatile double* vp = g_part;
        const int tid = threadIdx.x;
        double v0 = 0.0;
#pragma unroll
        for (int i = 0; i < NBLK / THREADS; i++) v0 += vp[tid + i * THREADS];
#pragma unroll
        for (int off = 16; off; off >>= 1) v0 += __shfl_down_sync(0xffffffffu, v0, off);
        __shared__ double sred[WPB];
        if ((tid & 31) == 0) sred[tid >> 5] = v0;
        __syncthreads();
        if (tid == 0) {
            double tot = 0.0;
#pragma unroll
            for (int w = 0; w < WPB; w++) tot += sred[w];
            out[0] = (float)tot;
        }
    }
}

extern "C" void kernel_launch(void* const* d_in, const int* in_sizes, int n_in,
                              void* d_out, int out_size) {
    const float4* x = (const float4*)d_in[0];   // clust_space [B*NPER, 4], 16B rows
    // d_in[1] (batch_idx) is sorted with equal group sizes -> pure reshape, unused.
    llfill_fused_kernel<<<NBLK, THREADS>>>(x, (float*)d_out);
}

// round 16
// speedup vs baseline: 1.0376x; 1.0376x over previous
#include <cuda_runtime.h>
#include <cuda_bf16.h>
#include <math.h>

#define NB   4096
#define NPER 2000
#define WPB  4                    // warps (events) per block
#define THREADS (WPB * 32)        // 128
#define NBLK (NB / WPB)           // 1024 blocks -> 148*6+136: near-perfect wave balance
#define BATCH 6                   // explicit front-batched LDG.128 per iteration

// Scratch (no device allocation allowed anywhere).
__device__ double g_part[NBLK];
__device__ unsigned int g_cnt = 0;

#define ACCUM(v)                                   \
    do {                                           \
        acc[0] += (v).x; acc[1] += (v).y;          \
        acc[2] += (v).z; acc[3] += (v).w;          \
        acc[4]  = fmaf((v).x, (v).x, acc[4]);      \
        acc[5]  = fmaf((v).x, (v).y, acc[5]);      \
        acc[6]  = fmaf((v).x, (v).z, acc[6]);      \
        acc[7]  = fmaf((v).x, (v).w, acc[7]);      \
        acc[8]  = fmaf((v).y, (v).y, acc[8]);      \
        acc[9]  = fmaf((v).y, (v).z, acc[9]);      \
        acc[10] = fmaf((v).y, (v).w, acc[10]);     \
        acc[11] = fmaf((v).z, (v).z, acc[11]);     \
        acc[12] = fmaf((v).z, (v).w, acc[12]);     \
        acc[13] = fmaf((v).w, (v).w, acc[13]);     \
    } while (0)

__global__ void __launch_bounds__(THREADS, 8) llfill_fused_kernel(
        const float4* __restrict__ x, float* __restrict__ out) {
    const int lane = threadIdx.x & 31;
    const int warp = threadIdx.x >> 5;
    const int b = blockIdx.x * WPB + warp;          // one warp per event
    const float4* base = x + (size_t)b * NPER + lane;

    // 14 accumulators: sums x,y,z,w; moments xx,xy,xz,xw,yy,yz,yw,zz,zw,ww
    float acc[14];
#pragma unroll
    for (int j = 0; j < 14; j++) acc[j] = 0.0f;

    // 2000 = 62*32 + 16.  62 = 10*BATCH + 2.
    float4 v[BATCH];
    for (int kk = 0; kk < 10; kk++) {
        const float4* p = base + (size_t)(32 * BATCH) * kk;
#pragma unroll
        for (int u = 0; u < BATCH; u++) v[u] = __ldg(p + 32 * u);
#pragma unroll
        for (int u = 0; u < BATCH; u++) ACCUM(v[u]);
    }
    {   // iterations 60, 61
        float4 a0 = __ldg(base + 32 * 60);
        float4 a1 = __ldg(base + 32 * 61);
        ACCUM(a0); ACCUM(a1);
    }
    if (lane < 16) {                                // 16-row tail
        float4 a = __ldg(x + (size_t)b * NPER + 1984 + lane);
        ACCUM(a);
    }

    // Warp shuffle reduce of the 14 moments.
#pragma unroll
    for (int j = 0; j < 14; j++) {
        float s = acc[j];
#pragma unroll
        for (int off = 16; off; off >>= 1) s += __shfl_down_sync(0xffffffffu, s, off);
        acc[j] = s;
    }

    __shared__ float spen[WPB];

    if (lane == 0) {
        const float invN = 1.0f / (float)NPER;
        const float m0 = acc[0] * invN, m1 = acc[1] * invN;
        const float m2 = acc[2] * invN, m3 = acc[3] * invN;

        // Covariance (symmetric), then shift by mu = trace/4 so tr(A)=0.
        float a00 = acc[4]  * invN - m0 * m0;
        float a01 = acc[5]  * invN - m0 * m1;
        float a02 = acc[6]  * invN - m0 * m2;
        float a03 = acc[7]  * invN - m0 * m3;
        float a11 = acc[8]  * invN - m1 * m1;
        float a12 = acc[9]  * invN - m1 * m2;
        float a13 = acc[10] * invN - m1 * m3;
        float a22 = acc[11] * invN - m2 * m2;
        float a23 = acc[12] * invN - m2 * m3;
        float a33 = acc[13] * invN - m3 * m3;

        const float mu = 0.25f * (a00 + a11 + a22 + a33);
        a00 -= mu; a11 -= mu; a22 -= mu; a33 -= mu;

        // p2 = tr(A^2) = sum_ij A_ij^2 (symmetric).
        float offsq = a01*a01 + a02*a02 + a03*a03 + a12*a12 + a13*a13 + a23*a23;
        float p2 = a00*a00 + a11*a11 + a22*a22 + a33*a33 + 2.0f * offsq;

        // B = A^2 (symmetric, 10 entries).
        float b00 = a00*a00 + a01*a01 + a02*a02 + a03*a03;
        float b11 = a01*a01 + a11*a11 + a12*a12 + a13*a13;
        float b22 = a02*a02 + a12*a12 + a22*a22 + a23*a23;
        float b33 = a03*a03 + a13*a13 + a23*a23 + a33*a33;
        float b01 = a00*a01 + a01*a11 + a02*a12 + a03*a13;
        float b02 = a00*a02 + a01*a12 + a02*a22 + a03*a23;
        float b03 = a00*a03 + a01*a13 + a02*a23 + a03*a33;
        float b12 = a01*a02 + a11*a12 + a12*a22 + a13*a23;
        float b13 = a01*a03 + a11*a13 + a12*a23 + a13*a33;
        float b23 = a02*a03 + a12*a13 + a22*a23 + a23*a33;

        // p3 = tr(A^3) = sum_ij B_ij A_ij ; p4 = tr(A^4) = sum_ij B_ij^2.
        float p3 = b00*a00 + b11*a11 + b22*a22 + b33*a33
                 + 2.0f * (b01*a01 + b02*a02 + b03*a03 + b12*a12 + b13*a13 + b23*a23);
        float p4 = b00*b00 + b11*b11 + b22*b22 + b33*b33
                 + 2.0f * (b01*b01 + b02*b02 + b03*b03 + b12*b12 + b13*b13 + b23*b23);

        // Char poly of trace-free A: l^4 + e2 l^2 - e3 l + e4 (Newton identities, e1=0).
        float e2 = -0.5f * p2;
        float e3 = p3 * (1.0f / 3.0f);
        float e4 = 0.25f * fmaf(0.5f * p2, p2, -p4);

        // Newton from below the smallest root: all roots real, start
        // l0 = -sqrt(p2) <= lmin (tr=0 => lmin <= 0). Monotone convergence.
        float l = -sqrtf(p2) * 1.000001f - 1e-12f;
#pragma unroll
        for (int it = 0; it < 16; it++) {
            float t  = l * l;
            float pv = fmaf(t + e2, t, fmaf(-e3, l, e4));
            float dv = fmaf(fmaf(4.0f, t, 2.0f * e2), l, -e3);
            l -= __fdividef(pv, dv);
        }

        float eigmin = mu + l;                          // min eigenvalue of cov
        float r = mu / (eigmin + 1e-6f) - 1.0f;         // mean(eig) == trace/4 == mu
        spen[warp] = logf(fmaf(r, r, 1.0f));
    }
    __syncthreads();

    // Per-block partial (fixed order -> deterministic), last-block final reduce.
    __shared__ bool is_last;
    if (threadIdx.x == 0) {
        double s = 0.0;
#pragma unroll
        for (int w = 0; w < WPB; w++) s += (double)spen[w];
        g_part[blockIdx.x] = s;
        __threadfence();
        unsigned int t = atomicInc(&g_cnt, NBLK - 1);   // wraps to 0 each launch
        is_last = (t == NBLK - 1);
    }
    __syncthreads();

    if (is_last) {
        // 128 threads reduce 1024 doubles with a fixed tree (deterministic).
        volatile double* vp = g_part;
        const int tid = threadIdx.x;
        double v0 = 0.0;
#pragma unroll
        for (int i = 0; i < NBLK / THREADS; i++) v0 += vp[tid + i * THREADS];
#pragma unroll
        for (int off = 16; off; off >>= 1) v0 += __shfl_down_sync(0xffffffffu, v0, off);
        __shared__ double sred[WPB];
        if ((tid & 31) == 0) sred[tid >> 5] = v0;
        __syncthreads();
        if (tid == 0) {
            double tot = 0.0;
#pragma unroll
            for (int w = 0; w < WPB; w++) tot += sred[w];
            out[0] = (float)tot;
        }
    }
}

extern "C" void kernel_launch(void* const* d_in, const int* in_sizes, int n_in,
                              void* d_out, int out_size) {
    const float4* x = (const float4*)d_in[0];   // clust_space [B*NPER, 4], 16B rows
    // d_in[1] (batch_idx) is sorted with equal group sizes -> pure reshape, unused.
    llfill_fused_kernel<<<NBLK, THREADS>>>(x, (float*)d_out);
}

// round 17
// speedup vs baseline: 1.0630x; 1.0245x over previous
#include <cuda_runtime.h>
#include <cuda_bf16.h>
#include <math.h>

#define NB   4096
#define NPER 2000
#define WPB  4                    // warps (events) per block
#define THREADS (WPB * 32)        // 128
#define NBLK (NB / WPB)           // 1024 blocks -> near-perfect wave balance
#define BATCH 8                   // explicit front-batched LDG.128 per iteration

// Scratch (no device allocation allowed anywhere).
__device__ double g_part[NBLK];
__device__ unsigned int g_cnt = 0;

#define ACCUM(v)                                   \
    do {                                           \
        acc[0] += (v).x; acc[1] += (v).y;          \
        acc[2] += (v).z; acc[3] += (v).w;          \
        acc[4]  = fmaf((v).x, (v).x, acc[4]);      \
        acc[5]  = fmaf((v).x, (v).y, acc[5]);      \
        acc[6]  = fmaf((v).x, (v).z, acc[6]);      \
        acc[7]  = fmaf((v).x, (v).w, acc[7]);      \
        acc[8]  = fmaf((v).y, (v).y, acc[8]);      \
        acc[9]  = fmaf((v).y, (v).z, acc[9]);      \
        acc[10] = fmaf((v).y, (v).w, acc[10]);     \
        acc[11] = fmaf((v).z, (v).z, acc[11]);     \
        acc[12] = fmaf((v).z, (v).w, acc[12]);     \
        acc[13] = fmaf((v).w, (v).w, acc[13]);     \
    } while (0)

__global__ void __launch_bounds__(THREADS, 7) llfill_fused_kernel(
        const float4* __restrict__ x, float* __restrict__ out) {
    const int lane = threadIdx.x & 31;
    const int warp = threadIdx.x >> 5;
    const int b = blockIdx.x * WPB + warp;          // one warp per event
    const float4* base = x + (size_t)b * NPER + lane;

    // 14 accumulators: sums x,y,z,w; moments xx,xy,xz,xw,yy,yz,yw,zz,zw,ww
    float acc[14];
#pragma unroll
    for (int j = 0; j < 14; j++) acc[j] = 0.0f;

    // 2000 = 62*32 + 16.  62 = 7*BATCH + 6.
    float4 v[BATCH];
    for (int kk = 0; kk < 7; kk++) {
        const float4* p = base + (size_t)(32 * BATCH) * kk;
#pragma unroll
        for (int u = 0; u < BATCH; u++) v[u] = __ldg(p + 32 * u);
#pragma unroll
        for (int u = 0; u < BATCH; u++) ACCUM(v[u]);
    }
    {   // iterations 56..61 (6 strides) + 16-row tail, all front-batched
        const float4* p = base + 32 * 56;
#pragma unroll
        for (int u = 0; u < 6; u++) v[u] = __ldg(p + 32 * u);
        const bool hast = (lane < 16);
        float4 at;
        if (hast) at = __ldg(x + (size_t)b * NPER + 1984 + lane);
#pragma unroll
        for (int u = 0; u < 6; u++) ACCUM(v[u]);
        if (hast) ACCUM(at);
    }

    // Warp shuffle reduce of the 14 moments.
#pragma unroll
    for (int j = 0; j < 14; j++) {
        float s = acc[j];
#pragma unroll
        for (int off = 16; off; off >>= 1) s += __shfl_down_sync(0xffffffffu, s, off);
        acc[j] = s;
    }

    __shared__ float spen[WPB];

    if (lane == 0) {
        const float invN = 1.0f / (float)NPER;
        const float m0 = acc[0] * invN, m1 = acc[1] * invN;
        const float m2 = acc[2] * invN, m3 = acc[3] * invN;

        // Covariance (symmetric), then shift by mu = trace/4 so tr(A)=0.
        float a00 = acc[4]  * invN - m0 * m0;
        float a01 = acc[5]  * invN - m0 * m1;
        float a02 = acc[6]  * invN - m0 * m2;
        float a03 = acc[7]  * invN - m0 * m3;
        float a11 = acc[8]  * invN - m1 * m1;
        float a12 = acc[9]  * invN - m1 * m2;
        float a13 = acc[10] * invN - m1 * m3;
        float a22 = acc[11] * invN - m2 * m2;
        float a23 = acc[12] * invN - m2 * m3;
        float a33 = acc[13] * invN - m3 * m3;

        const float mu = 0.25f * (a00 + a11 + a22 + a33);
        a00 -= mu; a11 -= mu; a22 -= mu; a33 -= mu;

        // p2 = tr(A^2) = sum_ij A_ij^2 (symmetric).
        float offsq = a01*a01 + a02*a02 + a03*a03 + a12*a12 + a13*a13 + a23*a23;
        float p2 = a00*a00 + a11*a11 + a22*a22 + a33*a33 + 2.0f * offsq;

        // B = A^2 (symmetric, 10 entries).
        float b00 = a00*a00 + a01*a01 + a02*a02 + a03*a03;
        float b11 = a01*a01 + a11*a11 + a12*a12 + a13*a13;
        float b22 = a02*a02 + a12*a12 + a22*a22 + a23*a23;
        float b33 = a03*a03 + a13*a13 + a23*a23 + a33*a33;
        float b01 = a00*a01 + a01*a11 + a02*a12 + a03*a13;
        float b02 = a00*a02 + a01*a12 + a02*a22 + a03*a23;
        float b03 = a00*a03 + a01*a13 + a02*a23 + a03*a33;
        float b12 = a01*a02 + a11*a12 + a12*a22 + a13*a23;
        float b13 = a01*a03 + a11*a13 + a12*a23 + a13*a33;
        float b23 = a02*a03 + a12*a13 + a22*a23 + a23*a33;

        // p3 = tr(A^3) = sum_ij B_ij A_ij ; p4 = tr(A^4) = sum_ij B_ij^2.
        float p3 = b00*a00 + b11*a11 + b22*a22 + b33*a33
                 + 2.0f * (b01*a01 + b02*a02 + b03*a03 + b12*a12 + b13*a13 + b23*a23);
        float p4 = b00*b00 + b11*b11 + b22*b22 + b33*b33
                 + 2.0f * (b01*b01 + b02*b02 + b03*b03 + b12*b12 + b13*b13 + b23*b23);

        // Char poly of trace-free A: l^4 + e2 l^2 - e3 l + e4 (Newton identities, e1=0).
        float e2 = -0.5f * p2;
        float e3 = p3 * (1.0f / 3.0f);
        float e4 = 0.25f * fmaf(0.5f * p2, p2, -p4);

        // Newton from below the smallest root: all roots real, start
        // l0 = -sqrt(p2) <= lmin (tr=0 => lmin <= 0). Monotone convergence.
        float l = -sqrtf(p2) * 1.000001f - 1e-12f;
#pragma unroll
        for (int it = 0; it < 16; it++) {
            float t  = l * l;
            float pv = fmaf(t + e2, t, fmaf(-e3, l, e4));
            float dv = fmaf(fmaf(4.0f, t, 2.0f * e2), l, -e3);
            l -= __fdividef(pv, dv);
        }

        float eigmin = mu + l;                          // min eigenvalue of cov
        float r = mu / (eigmin + 1e-6f) - 1.0f;         // mean(eig) == trace/4 == mu
        spen[warp] = logf(fmaf(r, r, 1.0f));
    }
    __syncthreads();

    // Per-block partial (fixed order -> deterministic), last-block final reduce.
    __shared__ bool is_last;
    if (threadIdx.x == 0) {
        double s = 0.0;
#pragma unroll
        for (int w = 0; w < WPB; w++) s += (double)spen[w];
        g_part[blockIdx.x] = s;
        __threadfence();
        unsigned int t = atomicInc(&g_cnt, NBLK - 1);   // wraps to 0 each launch
        is_last = (t == NBLK - 1);
    }
    __syncthreads();

    if (is_last) {
        // 128 threads reduce 1024 doubles with a fixed tree (deterministic).
        volatile double* vp = g_part;
        const int tid = threadIdx.x;
        double v0 = 0.0;
#pragma unroll
        for (int i = 0; i < NBLK / THREADS; i++) v0 += vp[tid + i * THREADS];
#pragma unroll
        for (int off = 16; off; off >>= 1) v0 += __shfl_down_sync(0xffffffffu, v0, off);
        __shared__ double sred[WPB];
        if ((tid & 31) == 0) sred[tid >> 5] = v0;
        __syncthreads();
        if (tid == 0) {
            double tot = 0.0;
#pragma unroll
            for (int w = 0; w < WPB; w++) tot += sred[w];
            out[0] = (float)tot;
        }
    }
}

extern "C" void kernel_launch(void* const* d_in, const int* in_sizes, int n_in,
                              void* d_out, int out_size) {
    const float4* x = (const float4*)d_in[0];   // clust_space [B*NPER, 4], 16B rows
    // d_in[1] (batch_idx) is sorted with equal group sizes -> pure reshape, unused.
    llfill_fused_kernel<<<NBLK, THREADS>>>(x, (float*)d_out);
}